// round 2
// baseline (speedup 1.0000x reference)
#include <cuda_runtime.h>
#include <cuda_bf16.h>
#include <cstdint>
#include <math.h>

// Problem constants
#define N_ROWS 4096
#define DIM    1024
#define VOCAB  50257

// GEMM tiling
#define BM 128
#define BN 128
#define BK 32
#define SSTR 40          // smem row stride in bf16 (32 + 8 pad) -> conflict-free frag loads
#define VT  ((VOCAB + BN - 1) / BN)   // 393 vocab tiles
#define MT  (N_ROWS / BM)             // 32 row tiles

// ---------------- device scratch (no allocations allowed) ----------------
static __device__ __align__(16) __nv_bfloat16 g_Wbf[(size_t)VOCAB * DIM]; // ~103 MB
static __device__ __align__(16) __nv_bfloat16 g_Xbf[(size_t)N_ROWS * DIM];
static __device__ float g_pm[(size_t)VT * N_ROWS];
static __device__ float g_ps[(size_t)VT * N_ROWS];
static __device__ float g_tl[N_ROWS];
static __device__ float g_loss[N_ROWS];
static __device__ int   g_is64;   // 1 if target buffer is int64, 0 if int32

// ---------------- target dtype detection ----------------
// Reads the first 2048 8-byte words (safe even if the buffer is 4096 int32 =
// 16KB). If all are valid labels in [0, VOCAB), the buffer is int64; an int32
// buffer would need 2048 odd-position labels to all be exactly 0.
__global__ void detect_kernel(const void* __restrict__ t) {
    __shared__ int ok;
    if (threadIdx.x == 0) ok = 1;
    __syncthreads();
    const long long* p = (const long long*)t;
    int bad = 0;
    for (int i = threadIdx.x; i < 2048; i += 256) {
        long long v = p[i];
        if (v < 0 || v >= VOCAB) bad = 1;
    }
    if (bad) ok = 0;   // benign race: any writer writes 0
    __syncthreads();
    if (threadIdx.x == 0) g_is64 = ok;
}

__device__ __forceinline__ long long load_target(const void* tgt, int row) {
    long long t;
    if (g_is64) t = ((const long long*)tgt)[row];
    else        t = (long long)((const int*)tgt)[row];
    // clamp: guarantees no OOB even if detection is somehow wrong
    if (t < 0) t = 0;
    if (t >= VOCAB) t = VOCAB - 1;
    return t;
}

// ---------------- fp32 -> bf16 conversion ----------------
__global__ void cvt_kernel(const float* __restrict__ in, long long n4, int which) {
    long long i = (long long)blockIdx.x * blockDim.x + threadIdx.x;
    if (i >= n4) return;
    float4 v = ((const float4*)in)[i];
    __nv_bfloat16* out = which ? g_Xbf : g_Wbf;
    __nv_bfloat162* o2 = (__nv_bfloat162*)out;
    o2[2 * i]     = __halves2bfloat162(__float2bfloat16(v.x), __float2bfloat16(v.y));
    o2[2 * i + 1] = __halves2bfloat162(__float2bfloat16(v.z), __float2bfloat16(v.w));
}

// ---------------- target logits: full fp32 dot per row ----------------
__global__ void tlogit_kernel(const float* __restrict__ x,
                              const float* __restrict__ w,
                              const void* __restrict__ tgt) {
    int row = blockIdx.x;
    long long t = load_target(tgt, row);
    const float* xr = x + (size_t)row * DIM;
    const float* wr = w + (size_t)t * DIM;
    float acc = 0.f;
    for (int k = threadIdx.x; k < DIM; k += 128) acc += xr[k] * wr[k];
    // warp reduce
    #pragma unroll
    for (int off = 16; off > 0; off >>= 1)
        acc += __shfl_down_sync(0xffffffffu, acc, off);
    __shared__ float red[4];
    int lane = threadIdx.x & 31, wid = threadIdx.x >> 5;
    if (lane == 0) red[wid] = acc;
    __syncthreads();
    if (threadIdx.x == 0)
        g_tl[row] = red[0] + red[1] + red[2] + red[3];
}

// ---------------- main fused GEMM + per-tile (max, sumexp) ----------------
__device__ __forceinline__ void mma_bf16(float c[4], uint32_t a0, uint32_t a1,
                                         uint32_t a2, uint32_t a3,
                                         uint32_t b0, uint32_t b1) {
    asm volatile(
        "mma.sync.aligned.m16n8k16.row.col.f32.bf16.bf16.f32 "
        "{%0,%1,%2,%3}, {%4,%5,%6,%7}, {%8,%9}, {%0,%1,%2,%3};\n"
        : "+f"(c[0]), "+f"(c[1]), "+f"(c[2]), "+f"(c[3])
        : "r"(a0), "r"(a1), "r"(a2), "r"(a3), "r"(b0), "r"(b1));
}

__global__ void __launch_bounds__(256) lse_kernel() {
    const int tid  = threadIdx.x;
    const int bm   = blockIdx.x;   // row tile  (fast dim -> W slice reused via L2)
    const int bv   = blockIdx.y;   // vocab tile
    const int lane = tid & 31;
    const int wid  = tid >> 5;
    const int wm   = wid & 1;      // warp row (2 x 64 rows)
    const int wn   = wid >> 1;     // warp col (4 x 32 cols)

    __shared__ __align__(16) __nv_bfloat16 sA[2][BM * SSTR];
    __shared__ __align__(16) __nv_bfloat16 sB[2][BN * SSTR];
    __shared__ float red_m[BM][4];
    __shared__ float red_s[BM][4];

    float c[4][4][4];
    #pragma unroll
    for (int i = 0; i < 4; ++i)
        #pragma unroll
        for (int j = 0; j < 4; ++j)
            #pragma unroll
            for (int k = 0; k < 4; ++k) c[i][j][k] = 0.f;

    // global->smem staging: each thread moves 2 uint4 for A and 2 for B per stage
    const int lr  = tid >> 2;        // 0..63
    const int lkc = (tid & 3) * 8;   // 0,8,16,24
    const size_t aRow0 = (size_t)(bm * BM + lr) * DIM;
    const size_t aRow1 = (size_t)(bm * BM + 64 + lr) * DIM;
    const int v0 = bv * BN + lr;
    const int v1 = v0 + 64;
    const bool v0ok = v0 < VOCAB;
    const bool v1ok = v1 < VOCAB;
    const size_t bRow0 = (size_t)v0 * DIM;
    const size_t bRow1 = (size_t)v1 * DIM;

    uint4 ra0, ra1, rb0, rb1;
    const uint4 z4 = make_uint4(0, 0, 0, 0);

#define LDG_STAGE(S) do {                                                       \
        int k0 = (S) * BK + lkc;                                                \
        ra0 = *(const uint4*)&g_Xbf[aRow0 + k0];                                \
        ra1 = *(const uint4*)&g_Xbf[aRow1 + k0];                                \
        rb0 = v0ok ? *(const uint4*)&g_Wbf[bRow0 + k0] : z4;                    \
        rb1 = v1ok ? *(const uint4*)&g_Wbf[bRow1 + k0] : z4;                    \
    } while (0)

#define STS_STAGE(BUF) do {                                                     \
        *(uint4*)&sA[BUF][lr * SSTR + lkc]        = ra0;                        \
        *(uint4*)&sA[BUF][(lr + 64) * SSTR + lkc] = ra1;                        \
        *(uint4*)&sB[BUF][lr * SSTR + lkc]        = rb0;                        \
        *(uint4*)&sB[BUF][(lr + 64) * SSTR + lkc] = rb1;                        \
    } while (0)

    LDG_STAGE(0);
    STS_STAGE(0);
    __syncthreads();

    const int NSTAGES = DIM / BK;  // 32
    for (int s = 0; s < NSTAGES; ++s) {
        if (s + 1 < NSTAGES) LDG_STAGE(s + 1);
        const int buf = s & 1;
        #pragma unroll
        for (int kk = 0; kk < BK; kk += 16) {
            uint32_t af[4][4];
            uint32_t bfr[4][2];
            #pragma unroll
            for (int mi = 0; mi < 4; ++mi) {
                int rr = wm * 64 + mi * 16 + (lane >> 2);
                const __nv_bfloat16* base = &sA[buf][rr * SSTR + kk + (lane & 3) * 2];
                af[mi][0] = *(const uint32_t*)(base);
                af[mi][1] = *(const uint32_t*)(base + 8 * SSTR);
                af[mi][2] = *(const uint32_t*)(base + 8);
                af[mi][3] = *(const uint32_t*)(base + 8 * SSTR + 8);
            }
            #pragma unroll
            for (int ni = 0; ni < 4; ++ni) {
                int cc = wn * 32 + ni * 8 + (lane >> 2);
                const __nv_bfloat16* bb = &sB[buf][cc * SSTR + kk + (lane & 3) * 2];
                bfr[ni][0] = *(const uint32_t*)(bb);
                bfr[ni][1] = *(const uint32_t*)(bb + 8);
            }
            #pragma unroll
            for (int mi = 0; mi < 4; ++mi)
                #pragma unroll
                for (int ni = 0; ni < 4; ++ni)
                    mma_bf16(c[mi][ni], af[mi][0], af[mi][1], af[mi][2], af[mi][3],
                             bfr[ni][0], bfr[ni][1]);
        }
        if (s + 1 < NSTAGES) {
            STS_STAGE((s + 1) & 1);
            __syncthreads();
        }
    }

    // ---------- epilogue: per-row (max, sumexp) over this 128-col tile ----------
    const int colBase = bv * BN + wn * 32 + (lane & 3) * 2;

    // phase 1: per-warp-chunk row max
    #pragma unroll
    for (int mi = 0; mi < 4; ++mi) {
        int r0 = wm * 64 + mi * 16 + (lane >> 2);
        float mx0 = -1e30f, mx1 = -1e30f;
        #pragma unroll
        for (int ni = 0; ni < 4; ++ni) {
            int col = colBase + ni * 8;
            if (col < VOCAB)     { mx0 = fmaxf(mx0, c[mi][ni][0]); mx1 = fmaxf(mx1, c[mi][ni][2]); }
            if (col + 1 < VOCAB) { mx0 = fmaxf(mx0, c[mi][ni][1]); mx1 = fmaxf(mx1, c[mi][ni][3]); }
        }
        mx0 = fmaxf(mx0, __shfl_xor_sync(0xffffffffu, mx0, 1));
        mx0 = fmaxf(mx0, __shfl_xor_sync(0xffffffffu, mx0, 2));
        mx1 = fmaxf(mx1, __shfl_xor_sync(0xffffffffu, mx1, 1));
        mx1 = fmaxf(mx1, __shfl_xor_sync(0xffffffffu, mx1, 2));
        if ((lane & 3) == 0) {
            red_m[r0][wn]     = mx0;
            red_m[r0 + 8][wn] = mx1;
        }
    }
    __syncthreads();

    // phase 2: sum exp(v - row_max) using the tile-wide row max
    #pragma unroll
    for (int mi = 0; mi < 4; ++mi) {
        int r0 = wm * 64 + mi * 16 + (lane >> 2);
        float rm0 = fmaxf(fmaxf(red_m[r0][0], red_m[r0][1]),
                          fmaxf(red_m[r0][2], red_m[r0][3]));
        float rm1 = fmaxf(fmaxf(red_m[r0 + 8][0], red_m[r0 + 8][1]),
                          fmaxf(red_m[r0 + 8][2], red_m[r0 + 8][3]));
        float s0 = 0.f, s1 = 0.f;
        #pragma unroll
        for (int ni = 0; ni < 4; ++ni) {
            int col = colBase + ni * 8;
            if (col < VOCAB)     { s0 += expf(c[mi][ni][0] - rm0); s1 += expf(c[mi][ni][2] - rm1); }
            if (col + 1 < VOCAB) { s0 += expf(c[mi][ni][1] - rm0); s1 += expf(c[mi][ni][3] - rm1); }
        }
        s0 += __shfl_xor_sync(0xffffffffu, s0, 1);
        s0 += __shfl_xor_sync(0xffffffffu, s0, 2);
        s1 += __shfl_xor_sync(0xffffffffu, s1, 1);
        s1 += __shfl_xor_sync(0xffffffffu, s1, 2);
        if ((lane & 3) == 0) {
            red_s[r0][wn]     = s0;
            red_s[r0 + 8][wn] = s1;
        }
    }
    __syncthreads();

    if (tid < BM) {
        float rm = fmaxf(fmaxf(red_m[tid][0], red_m[tid][1]),
                         fmaxf(red_m[tid][2], red_m[tid][3]));
        float rs = red_s[tid][0] + red_s[tid][1] + red_s[tid][2] + red_s[tid][3];
        size_t row = (size_t)bm * BM + tid;
        g_pm[(size_t)bv * N_ROWS + row] = rm;
        g_ps[(size_t)bv * N_ROWS + row] = rs;
    }
}

// ---------------- combine partial (m, s) -> per-row loss ----------------
__global__ void combine_kernel() {
    int row = blockIdx.x * blockDim.x + threadIdx.x;
    if (row >= N_ROWS) return;
    float m = -1e30f;
    for (int i = 0; i < VT; ++i)
        m = fmaxf(m, g_pm[(size_t)i * N_ROWS + row]);
    float s = 0.f;
    for (int i = 0; i < VT; ++i)
        s += g_ps[(size_t)i * N_ROWS + row] * expf(g_pm[(size_t)i * N_ROWS + row] - m);
    g_loss[row] = (m + logf(s)) - g_tl[row];
}

// ---------------- mean reduction ----------------
__global__ void reduce_kernel(float* out) {
    float acc = 0.f;
    for (int i = threadIdx.x; i < N_ROWS; i += 256) acc += g_loss[i];
    #pragma unroll
    for (int off = 16; off > 0; off >>= 1)
        acc += __shfl_down_sync(0xffffffffu, acc, off);
    __shared__ float red[8];
    int lane = threadIdx.x & 31, wid = threadIdx.x >> 5;
    if (lane == 0) red[wid] = acc;
    __syncthreads();
    if (threadIdx.x == 0) {
        float t = 0.f;
        #pragma unroll
        for (int i = 0; i < 8; ++i) t += red[i];
        out[0] = t * (1.0f / N_ROWS);
    }
}

// ---------------- launch ----------------
extern "C" void kernel_launch(void* const* d_in, const int* in_sizes, int n_in,
                              void* d_out, int out_size) {
    const float* x = nullptr;
    const float* w = nullptr;
    const void* tgt = nullptr;
    // identify inputs by element count (defensive against ordering)
    for (int i = 0; i < n_in; ++i) {
        long long sz = in_sizes[i];
        if (sz == (long long)N_ROWS * DIM)      x   = (const float*)d_in[i];
        else if (sz == (long long)VOCAB * DIM)  w   = (const float*)d_in[i];
        else if (sz == (long long)N_ROWS)       tgt = d_in[i];
    }
    if (!x)   x   = (const float*)d_in[0];
    if (!w)   w   = (const float*)d_in[1];
    if (!tgt) tgt = d_in[2];
    float* out = (float*)d_out;

    long long w4 = (long long)VOCAB * DIM / 4;
    long long x4 = (long long)N_ROWS * DIM / 4;
    detect_kernel<<<1, 256>>>(tgt);
    cvt_kernel<<<(unsigned)((w4 + 255) / 256), 256>>>(w, w4, 0);
    cvt_kernel<<<(unsigned)((x4 + 255) / 256), 256>>>(x, x4, 1);
    tlogit_kernel<<<N_ROWS, 128>>>(x, w, tgt);
    lse_kernel<<<dim3(MT, VT), 256>>>();
    combine_kernel<<<(N_ROWS + 255) / 256, 256>>>();
    reduce_kernel<<<1, 256>>>(out);
}

// round 4
// speedup vs baseline: 1.4409x; 1.4409x over previous
#include <cuda_runtime.h>
#include <cuda_bf16.h>
#include <cstdint>
#include <math.h>

// ---------------- problem constants ----------------
#define N_ROWS 4096
#define DIM    1024
#define VOCAB  50257

// GEMM tiling: CTA 128x256, K-chunk 64, 3-stage cp.async pipeline
#define BM 128
#define BN 256
#define BK 64
#define NSTAGE 3
#define VT2 ((VOCAB + BN - 1) / BN)   // 197 vocab tiles
#define MT  (N_ROWS / BM)             // 32 row tiles
#define NKT (DIM / BK)                // 16 K iterations

// smem: per stage A(128x128B=16KB) + B(256x128B=32KB) = 48KB; 3 stages + 4KB red
#define ST_B      16384
#define STAGE_SZ  49152
#define RED_OFF   (NSTAGE * STAGE_SZ)          // 147456
#define SM_TOTAL  (RED_OFF + 4096)             // 151552

// ---------------- device scratch ----------------
static __device__ __align__(16) __nv_bfloat16 g_Wbf[(size_t)VOCAB * DIM];
static __device__ __align__(16) __nv_bfloat16 g_Xbf[(size_t)N_ROWS * DIM];
static __device__ float g_pm[(size_t)VT2 * N_ROWS];
static __device__ float g_ps[(size_t)VT2 * N_ROWS];
static __device__ float g_tl[N_ROWS];
static __device__ float g_loss[N_ROWS];
static __device__ int   g_is64;

// ---------------- helpers ----------------
__device__ __forceinline__ uint32_t smem_u32(const void* p) {
    uint32_t a;
    asm("{ .reg .u64 t; cvta.to.shared.u64 t, %1; cvt.u32.u64 %0, t; }" : "=r"(a) : "l"(p));
    return a;
}
#define SWZ(x) ((x) ^ (((x) >> 3) & 0x70))

__device__ __forceinline__ void cp16(uint32_t dst, const void* src, int sz) {
    asm volatile("cp.async.cg.shared.global [%0], [%1], 16, %2;"
                 :: "r"(dst), "l"(src), "r"(sz) : "memory");
}
#define CP_COMMIT() asm volatile("cp.async.commit_group;" ::: "memory")
#define CP_WAIT1()  asm volatile("cp.async.wait_group 1;" ::: "memory")

__device__ __forceinline__ void ldsm4(uint32_t* r, uint32_t addr) {
    asm volatile("ldmatrix.sync.aligned.m8n8.x4.shared.b16 {%0,%1,%2,%3}, [%4];"
                 : "=r"(r[0]), "=r"(r[1]), "=r"(r[2]), "=r"(r[3]) : "r"(addr));
}
__device__ __forceinline__ void mma_bf16(float c[4], uint32_t a0, uint32_t a1,
                                         uint32_t a2, uint32_t a3,
                                         uint32_t b0, uint32_t b1) {
    asm volatile(
        "mma.sync.aligned.m16n8k16.row.col.f32.bf16.bf16.f32 "
        "{%0,%1,%2,%3}, {%4,%5,%6,%7}, {%8,%9}, {%0,%1,%2,%3};\n"
        : "+f"(c[0]), "+f"(c[1]), "+f"(c[2]), "+f"(c[3])
        : "r"(a0), "r"(a1), "r"(a2), "r"(a3), "r"(b0), "r"(b1));
}

// ---------------- target dtype detection ----------------
__global__ void detect_kernel(const void* __restrict__ t) {
    __shared__ int ok;
    if (threadIdx.x == 0) ok = 1;
    __syncthreads();
    const long long* p = (const long long*)t;
    int bad = 0;
    for (int i = threadIdx.x; i < 2048; i += 256) {
        long long v = p[i];
        if (v < 0 || v >= VOCAB) bad = 1;
    }
    if (bad) ok = 0;
    __syncthreads();
    if (threadIdx.x == 0) g_is64 = ok;
}
__device__ __forceinline__ long long load_target(const void* tgt, int row) {
    long long t = g_is64 ? ((const long long*)tgt)[row]
                         : (long long)((const int*)tgt)[row];
    if (t < 0) t = 0;
    if (t >= VOCAB) t = VOCAB - 1;
    return t;
}

// ---------------- fp32 -> bf16 (8 elems / thread) ----------------
__global__ void cvt_kernel(const float* __restrict__ in, long long n8, int which) {
    long long i = (long long)blockIdx.x * blockDim.x + threadIdx.x;
    if (i >= n8) return;
    float4 a = ((const float4*)in)[2 * i];
    float4 b = ((const float4*)in)[2 * i + 1];
    __nv_bfloat16* out = which ? g_Xbf : g_Wbf;
    __nv_bfloat162 r[4];
    r[0] = __halves2bfloat162(__float2bfloat16(a.x), __float2bfloat16(a.y));
    r[1] = __halves2bfloat162(__float2bfloat16(a.z), __float2bfloat16(a.w));
    r[2] = __halves2bfloat162(__float2bfloat16(b.x), __float2bfloat16(b.y));
    r[3] = __halves2bfloat162(__float2bfloat16(b.z), __float2bfloat16(b.w));
    ((uint4*)out)[i] = *(uint4*)r;
}

// ---------------- target logits: fp32 dot ----------------
__global__ void tlogit_kernel(const float* __restrict__ x,
                              const float* __restrict__ w,
                              const void* __restrict__ tgt) {
    int row = blockIdx.x;
    long long t = load_target(tgt, row);
    const float* xr = x + (size_t)row * DIM;
    const float* wr = w + (size_t)t * DIM;
    float acc = 0.f;
    for (int k = threadIdx.x; k < DIM; k += 128) acc += xr[k] * wr[k];
    #pragma unroll
    for (int off = 16; off > 0; off >>= 1)
        acc += __shfl_down_sync(0xffffffffu, acc, off);
    __shared__ float red[4];
    int lane = threadIdx.x & 31, wid = threadIdx.x >> 5;
    if (lane == 0) red[wid] = acc;
    __syncthreads();
    if (threadIdx.x == 0) g_tl[row] = red[0] + red[1] + red[2] + red[3];
}

// ---------------- main fused GEMM + per-tile (max, sumexp) ----------------
__global__ void __launch_bounds__(256, 1) lse_kernel() {
    extern __shared__ char smem[];
    const uint32_t sb = smem_u32(smem);
    const int tid  = threadIdx.x;
    const int lane = tid & 31;
    const int wid  = tid >> 5;
    const int wm   = wid & 1;       // 2 warp rows x 64
    const int wn   = wid >> 1;      // 4 warp cols x 64
    const int bm   = blockIdx.x;
    const int bv   = blockIdx.y;

    float* red_m = (float*)(smem + RED_OFF);          // [128][4]
    float* red_s = (float*)(smem + RED_OFF + 2048);   // [128][4]

    // ---- cp.async source/dest precompute ----
    // A: 1024 16B chunks (128 rows x 8), B: 2048 chunks (256 rows x 8)
    uint32_t aDst[4]; size_t aSrc[4];
    uint32_t bDst[8]; const __nv_bfloat16* bSrc[8]; int bSz[8];
    #pragma unroll
    for (int i = 0; i < 4; ++i) {
        int idx = tid + 256 * i;
        int row = idx >> 3, c16 = idx & 7;
        aDst[i] = SWZ((uint32_t)(row * 128 + c16 * 16));
        aSrc[i] = (size_t)(bm * BM + row) * DIM + c16 * 8;
    }
    #pragma unroll
    for (int i = 0; i < 8; ++i) {
        int idx = tid + 256 * i;
        int row = idx >> 3, c16 = idx & 7;
        int vr = bv * BN + row;
        bDst[i] = SWZ((uint32_t)(row * 128 + c16 * 16));
        bSrc[i] = g_Wbf + (size_t)(vr < VOCAB ? vr : 0) * DIM + c16 * 8;
        bSz[i]  = vr < VOCAB ? 16 : 0;
    }

#define PRODUCE(KT) do {                                                       \
        int _kt = (KT);                                                        \
        uint32_t _d = sb + (uint32_t)(_kt % NSTAGE) * STAGE_SZ;                \
        const __nv_bfloat16* _a = g_Xbf + _kt * BK;                            \
        _Pragma("unroll")                                                      \
        for (int _i = 0; _i < 4; ++_i) cp16(_d + aDst[_i], _a + aSrc[_i], 16); \
        _Pragma("unroll")                                                      \
        for (int _i = 0; _i < 8; ++_i)                                         \
            cp16(_d + ST_B + bDst[_i], bSrc[_i] + _kt * BK, bSz[_i]);          \
    } while (0)

    // ---- fragment address components (ldmatrix, swizzled) ----
    // A: lanes 0-15 rows m0..m0+15, lanes 16-31 same rows, +16B col
    uint32_t aRowOff[4];
    #pragma unroll
    for (int mi = 0; mi < 4; ++mi)
        aRowOff[mi] = (uint32_t)((wm * 64 + mi * 16 + (lane & 15)) * 128);
    const uint32_t aColSel = (lane >> 4) * 16;
    // B: rows n0 + (lane&7) + ((lane>>4)&1)*8 ; col +16B if (lane>>3)&1
    uint32_t bRowOff[4];
    #pragma unroll
    for (int nt = 0; nt < 4; ++nt)
        bRowOff[nt] = (uint32_t)((wn * 64 + nt * 16 + (lane & 7) + ((lane >> 4) & 1) * 8) * 128);
    const uint32_t bColSel = ((lane >> 3) & 1) * 16;

    float c[4][8][4];
    #pragma unroll
    for (int i = 0; i < 4; ++i)
        #pragma unroll
        for (int j = 0; j < 8; ++j)
            #pragma unroll
            for (int k = 0; k < 4; ++k) c[i][j][k] = 0.f;

    // ---- pipeline prologue ----
    PRODUCE(0); CP_COMMIT();
    PRODUCE(1); CP_COMMIT();
    CP_WAIT1();
    __syncthreads();

    // ---- mainloop ----
    for (int kt = 0; kt < NKT; ++kt) {
        if (kt + 2 < NKT) { PRODUCE(kt + 2); CP_COMMIT(); }
        const uint32_t sA = sb + (uint32_t)(kt % NSTAGE) * STAGE_SZ;
        const uint32_t sB = sA + ST_B;
        #pragma unroll
        for (int ks = 0; ks < 4; ++ks) {
            const uint32_t acol = ks * 32 + aColSel;
            const uint32_t bcol = ks * 32 + bColSel;
            uint32_t af[4][4];
            #pragma unroll
            for (int mi = 0; mi < 4; ++mi)
                ldsm4(af[mi], sA + SWZ(aRowOff[mi] + acol));
            #pragma unroll
            for (int nt = 0; nt < 4; ++nt) {
                uint32_t bf[4];
                ldsm4(bf, sB + SWZ(bRowOff[nt] + bcol));
                #pragma unroll
                for (int mi = 0; mi < 4; ++mi) {
                    mma_bf16(c[mi][2 * nt],     af[mi][0], af[mi][1], af[mi][2], af[mi][3], bf[0], bf[1]);
                    mma_bf16(c[mi][2 * nt + 1], af[mi][0], af[mi][1], af[mi][2], af[mi][3], bf[2], bf[3]);
                }
            }
        }
        if (kt + 2 < NKT) CP_WAIT1();
        __syncthreads();
    }
#undef PRODUCE

    // ---- epilogue: per-row (max, sumexp) over this 256-col tile ----
    const int colBase = bv * BN + wn * 64 + (lane & 3) * 2;

    #pragma unroll
    for (int mi = 0; mi < 4; ++mi) {
        int r0 = wm * 64 + mi * 16 + (lane >> 2);
        float mx0 = -1e30f, mx1 = -1e30f;
        #pragma unroll
        for (int ni = 0; ni < 8; ++ni) {
            int col = colBase + ni * 8;
            if (col < VOCAB)     { mx0 = fmaxf(mx0, c[mi][ni][0]); mx1 = fmaxf(mx1, c[mi][ni][2]); }
            if (col + 1 < VOCAB) { mx0 = fmaxf(mx0, c[mi][ni][1]); mx1 = fmaxf(mx1, c[mi][ni][3]); }
        }
        mx0 = fmaxf(mx0, __shfl_xor_sync(0xffffffffu, mx0, 1));
        mx0 = fmaxf(mx0, __shfl_xor_sync(0xffffffffu, mx0, 2));
        mx1 = fmaxf(mx1, __shfl_xor_sync(0xffffffffu, mx1, 1));
        mx1 = fmaxf(mx1, __shfl_xor_sync(0xffffffffu, mx1, 2));
        if ((lane & 3) == 0) {
            red_m[r0 * 4 + wn]       = mx0;
            red_m[(r0 + 8) * 4 + wn] = mx1;
        }
    }
    __syncthreads();

    #pragma unroll
    for (int mi = 0; mi < 4; ++mi) {
        int r0 = wm * 64 + mi * 16 + (lane >> 2);
        float rm0 = fmaxf(fmaxf(red_m[r0 * 4 + 0], red_m[r0 * 4 + 1]),
                          fmaxf(red_m[r0 * 4 + 2], red_m[r0 * 4 + 3]));
        float rm1 = fmaxf(fmaxf(red_m[(r0 + 8) * 4 + 0], red_m[(r0 + 8) * 4 + 1]),
                          fmaxf(red_m[(r0 + 8) * 4 + 2], red_m[(r0 + 8) * 4 + 3]));
        float s0 = 0.f, s1 = 0.f;
        #pragma unroll
        for (int ni = 0; ni < 8; ++ni) {
            int col = colBase + ni * 8;
            if (col < VOCAB)     { s0 += __expf(c[mi][ni][0] - rm0); s1 += __expf(c[mi][ni][2] - rm1); }
            if (col + 1 < VOCAB) { s0 += __expf(c[mi][ni][1] - rm0); s1 += __expf(c[mi][ni][3] - rm1); }
        }
        s0 += __shfl_xor_sync(0xffffffffu, s0, 1);
        s0 += __shfl_xor_sync(0xffffffffu, s0, 2);
        s1 += __shfl_xor_sync(0xffffffffu, s1, 1);
        s1 += __shfl_xor_sync(0xffffffffu, s1, 2);
        if ((lane & 3) == 0) {
            red_s[r0 * 4 + wn]       = s0;
            red_s[(r0 + 8) * 4 + wn] = s1;
        }
    }
    __syncthreads();

    if (tid < BM) {
        float rm = fmaxf(fmaxf(red_m[tid * 4 + 0], red_m[tid * 4 + 1]),
                         fmaxf(red_m[tid * 4 + 2], red_m[tid * 4 + 3]));
        float rs = red_s[tid * 4 + 0] + red_s[tid * 4 + 1] +
                   red_s[tid * 4 + 2] + red_s[tid * 4 + 3];
        size_t row = (size_t)bm * BM + tid;
        g_pm[(size_t)bv * N_ROWS + row] = rm;
        g_ps[(size_t)bv * N_ROWS + row] = rs;
    }
}

// ---------------- combine partial (m, s) -> per-row loss ----------------
__global__ void combine_kernel() {
    int row = blockIdx.x * blockDim.x + threadIdx.x;
    if (row >= N_ROWS) return;
    float m = -1e30f;
    for (int i = 0; i < VT2; ++i)
        m = fmaxf(m, g_pm[(size_t)i * N_ROWS + row]);
    float s = 0.f;
    for (int i = 0; i < VT2; ++i)
        s += g_ps[(size_t)i * N_ROWS + row] * expf(g_pm[(size_t)i * N_ROWS + row] - m);
    g_loss[row] = (m + logf(s)) - g_tl[row];
}

// ---------------- mean reduction ----------------
__global__ void reduce_kernel(float* out) {
    float acc = 0.f;
    for (int i = threadIdx.x; i < N_ROWS; i += 256) acc += g_loss[i];
    #pragma unroll
    for (int off = 16; off > 0; off >>= 1)
        acc += __shfl_down_sync(0xffffffffu, acc, off);
    __shared__ float red[8];
    int lane = threadIdx.x & 31, wid = threadIdx.x >> 5;
    if (lane == 0) red[wid] = acc;
    __syncthreads();
    if (threadIdx.x == 0) {
        float t = 0.f;
        #pragma unroll
        for (int i = 0; i < 8; ++i) t += red[i];
        out[0] = t * (1.0f / N_ROWS);
    }
}

// ---------------- launch ----------------
extern "C" void kernel_launch(void* const* d_in, const int* in_sizes, int n_in,
                              void* d_out, int out_size) {
    const float* x = nullptr;
    const float* w = nullptr;
    const void* tgt = nullptr;
    for (int i = 0; i < n_in; ++i) {
        long long sz = in_sizes[i];
        if (sz == (long long)N_ROWS * DIM)      x   = (const float*)d_in[i];
        else if (sz == (long long)VOCAB * DIM)  w   = (const float*)d_in[i];
        else if (sz == (long long)N_ROWS)       tgt = d_in[i];
    }
    if (!x)   x   = (const float*)d_in[0];
    if (!w)   w   = (const float*)d_in[1];
    if (!tgt) tgt = d_in[2];
    float* out = (float*)d_out;

    cudaFuncSetAttribute(lse_kernel,
                         cudaFuncAttributeMaxDynamicSharedMemorySize, SM_TOTAL);

    long long w8 = (long long)VOCAB * DIM / 8;
    long long x8 = (long long)N_ROWS * DIM / 8;
    detect_kernel<<<1, 256>>>(tgt);
    cvt_kernel<<<(unsigned)((w8 + 255) / 256), 256>>>(w, w8, 0);
    cvt_kernel<<<(unsigned)((x8 + 255) / 256), 256>>>(x, x8, 1);
    tlogit_kernel<<<N_ROWS, 128>>>(x, w, tgt);
    lse_kernel<<<dim3(MT, VT2), 256, SM_TOTAL>>>();
    combine_kernel<<<(N_ROWS + 255) / 256, 256>>>();
    reduce_kernel<<<1, 256>>>(out);
}

// round 5
// speedup vs baseline: 1.5003x; 1.0413x over previous
#include <cuda_runtime.h>
#include <cuda_bf16.h>
#include <cstdint>
#include <math.h>

// ---------------- problem constants ----------------
#define N_ROWS 4096
#define DIM    1024
#define VOCAB  50257

// GEMM tiling: CTA 128x256, K-chunk 64, 3-stage cp.async pipeline, 512 threads
#define BM 128
#define BN 256
#define BK 64
#define NSTAGE 3
#define VT2 ((VOCAB + BN - 1) / BN)   // 197 vocab tiles
#define MT  (N_ROWS / BM)             // 32 row tiles
#define NKT (DIM / BK)                // 16 K iterations

// smem: per stage A(128x128B=16KB) + B(256x128B=32KB) = 48KB; 3 stages + 8KB red
#define ST_B      16384
#define STAGE_SZ  49152
#define RED_OFF   (NSTAGE * STAGE_SZ)          // 147456
#define SM_TOTAL  (RED_OFF + 8192)             // 155648

// ---------------- device scratch ----------------
static __device__ __align__(16) __nv_bfloat16 g_Wbf[(size_t)VOCAB * DIM];
static __device__ __align__(16) __nv_bfloat16 g_Xbf[(size_t)N_ROWS * DIM];
static __device__ float g_pm[(size_t)VT2 * N_ROWS];
static __device__ float g_ps[(size_t)VT2 * N_ROWS];
static __device__ float g_tl[N_ROWS];
static __device__ float g_loss[N_ROWS];
static __device__ int   g_is64;

// ---------------- helpers ----------------
__device__ __forceinline__ uint32_t smem_u32(const void* p) {
    uint32_t a;
    asm("{ .reg .u64 t; cvta.to.shared.u64 t, %1; cvt.u32.u64 %0, t; }" : "=r"(a) : "l"(p));
    return a;
}
#define SWZ(x) ((x) ^ (((x) >> 3) & 0x70))

__device__ __forceinline__ void cp16(uint32_t dst, const void* src, int sz) {
    asm volatile("cp.async.cg.shared.global [%0], [%1], 16, %2;"
                 :: "r"(dst), "l"(src), "r"(sz) : "memory");
}
#define CP_COMMIT() asm volatile("cp.async.commit_group;" ::: "memory")
#define CP_WAIT1()  asm volatile("cp.async.wait_group 1;" ::: "memory")

__device__ __forceinline__ void ldsm4(uint32_t* r, uint32_t addr) {
    asm volatile("ldmatrix.sync.aligned.m8n8.x4.shared.b16 {%0,%1,%2,%3}, [%4];"
                 : "=r"(r[0]), "=r"(r[1]), "=r"(r[2]), "=r"(r[3]) : "r"(addr));
}
__device__ __forceinline__ void mma_bf16(float c[4], uint32_t a0, uint32_t a1,
                                         uint32_t a2, uint32_t a3,
                                         uint32_t b0, uint32_t b1) {
    asm volatile(
        "mma.sync.aligned.m16n8k16.row.col.f32.bf16.bf16.f32 "
        "{%0,%1,%2,%3}, {%4,%5,%6,%7}, {%8,%9}, {%0,%1,%2,%3};\n"
        : "+f"(c[0]), "+f"(c[1]), "+f"(c[2]), "+f"(c[3])
        : "r"(a0), "r"(a1), "r"(a2), "r"(a3), "r"(b0), "r"(b1));
}

// ---------------- target dtype detection ----------------
__global__ void detect_kernel(const void* __restrict__ t) {
    __shared__ int ok;
    if (threadIdx.x == 0) ok = 1;
    __syncthreads();
    const long long* p = (const long long*)t;
    int bad = 0;
    for (int i = threadIdx.x; i < 2048; i += 256) {
        long long v = p[i];
        if (v < 0 || v >= VOCAB) bad = 1;
    }
    if (bad) ok = 0;
    __syncthreads();
    if (threadIdx.x == 0) g_is64 = ok;
}
__device__ __forceinline__ long long load_target(const void* tgt, int row) {
    long long t = g_is64 ? ((const long long*)tgt)[row]
                         : (long long)((const int*)tgt)[row];
    if (t < 0) t = 0;
    if (t >= VOCAB) t = VOCAB - 1;
    return t;
}

// ---------------- fp32 -> bf16 (8 elems / thread) ----------------
__global__ void cvt_kernel(const float* __restrict__ in, long long n8, int which) {
    long long i = (long long)blockIdx.x * blockDim.x + threadIdx.x;
    if (i >= n8) return;
    float4 a = ((const float4*)in)[2 * i];
    float4 b = ((const float4*)in)[2 * i + 1];
    __nv_bfloat16* out = which ? g_Xbf : g_Wbf;
    __nv_bfloat162 r[4];
    r[0] = __halves2bfloat162(__float2bfloat16(a.x), __float2bfloat16(a.y));
    r[1] = __halves2bfloat162(__float2bfloat16(a.z), __float2bfloat16(a.w));
    r[2] = __halves2bfloat162(__float2bfloat16(b.x), __float2bfloat16(b.y));
    r[3] = __halves2bfloat162(__float2bfloat16(b.z), __float2bfloat16(b.w));
    ((uint4*)out)[i] = *(uint4*)r;
}

// ---------------- target logits: fp32 dot ----------------
__global__ void tlogit_kernel(const float* __restrict__ x,
                              const float* __restrict__ w,
                              const void* __restrict__ tgt) {
    int row = blockIdx.x;
    long long t = load_target(tgt, row);
    const float* xr = x + (size_t)row * DIM;
    const float* wr = w + (size_t)t * DIM;
    float acc = 0.f;
    for (int k = threadIdx.x; k < DIM; k += 128) acc += xr[k] * wr[k];
    #pragma unroll
    for (int off = 16; off > 0; off >>= 1)
        acc += __shfl_down_sync(0xffffffffu, acc, off);
    __shared__ float red[4];
    int lane = threadIdx.x & 31, wid = threadIdx.x >> 5;
    if (lane == 0) red[wid] = acc;
    __syncthreads();
    if (threadIdx.x == 0) g_tl[row] = red[0] + red[1] + red[2] + red[3];
}

// ---------------- main fused GEMM + per-tile (max, sumexp) ----------------
__global__ void __launch_bounds__(512, 1) lse_kernel() {
    extern __shared__ char smem[];
    const uint32_t sb = smem_u32(smem);
    const int tid  = threadIdx.x;
    const int lane = tid & 31;
    const int wid  = tid >> 5;      // 0..15
    const int wm   = wid & 1;       // 2 warp rows x 64
    const int wn   = wid >> 1;      // 8 warp cols x 32
    const int bm   = blockIdx.x;
    const int bv   = blockIdx.y;

    float* red_m = (float*)(smem + RED_OFF);          // [128][8]
    float* red_s = (float*)(smem + RED_OFF + 4096);   // [128][8]

    // ---- cp.async source/dest precompute ----
    // A: 1024 16B chunks (128 rows x 8) -> 2/thread; B: 2048 -> 4/thread
    uint32_t aDst[2]; size_t aSrc[2];
    uint32_t bDst[4]; const __nv_bfloat16* bSrc[4]; int bSz[4];
    #pragma unroll
    for (int i = 0; i < 2; ++i) {
        int idx = tid + 512 * i;
        int row = idx >> 3, c16 = idx & 7;
        aDst[i] = SWZ((uint32_t)(row * 128 + c16 * 16));
        aSrc[i] = (size_t)(bm * BM + row) * DIM + c16 * 8;
    }
    #pragma unroll
    for (int i = 0; i < 4; ++i) {
        int idx = tid + 512 * i;
        int row = idx >> 3, c16 = idx & 7;
        int vr = bv * BN + row;
        bDst[i] = SWZ((uint32_t)(row * 128 + c16 * 16));
        bSrc[i] = g_Wbf + (size_t)(vr < VOCAB ? vr : 0) * DIM + c16 * 8;
        bSz[i]  = vr < VOCAB ? 16 : 0;
    }

#define PRODUCE(KT) do {                                                       \
        int _kt = (KT);                                                        \
        uint32_t _d = sb + (uint32_t)(_kt % NSTAGE) * STAGE_SZ;                \
        const __nv_bfloat16* _a = g_Xbf + _kt * BK;                            \
        _Pragma("unroll")                                                      \
        for (int _i = 0; _i < 2; ++_i) cp16(_d + aDst[_i], _a + aSrc[_i], 16); \
        _Pragma("unroll")                                                      \
        for (int _i = 0; _i < 4; ++_i)                                         \
            cp16(_d + ST_B + bDst[_i], bSrc[_i] + _kt * BK, bSz[_i]);          \
    } while (0)

    // ---- fragment address components (ldmatrix, swizzled) ----
    uint32_t aRowOff[4];
    #pragma unroll
    for (int mi = 0; mi < 4; ++mi)
        aRowOff[mi] = (uint32_t)((wm * 64 + mi * 16 + (lane & 15)) * 128);
    const uint32_t aColSel = (lane >> 4) * 16;
    uint32_t bRowOff[2];
    #pragma unroll
    for (int nt = 0; nt < 2; ++nt)
        bRowOff[nt] = (uint32_t)((wn * 32 + nt * 16 + (lane & 7) + ((lane >> 4) & 1) * 8) * 128);
    const uint32_t bColSel = ((lane >> 3) & 1) * 16;

    float c[4][4][4];
    #pragma unroll
    for (int i = 0; i < 4; ++i)
        #pragma unroll
        for (int j = 0; j < 4; ++j)
            #pragma unroll
            for (int k = 0; k < 4; ++k) c[i][j][k] = 0.f;

    // ---- pipeline prologue ----
    PRODUCE(0); CP_COMMIT();
    PRODUCE(1); CP_COMMIT();
    CP_WAIT1();
    __syncthreads();

    // ---- mainloop ----
    for (int kt = 0; kt < NKT; ++kt) {
        if (kt + 2 < NKT) { PRODUCE(kt + 2); CP_COMMIT(); }
        const uint32_t sA = sb + (uint32_t)(kt % NSTAGE) * STAGE_SZ;
        const uint32_t sB = sA + ST_B;
        #pragma unroll
        for (int ks = 0; ks < 4; ++ks) {
            const uint32_t acol = ks * 32 + aColSel;
            const uint32_t bcol = ks * 32 + bColSel;
            uint32_t af[4][4];
            #pragma unroll
            for (int mi = 0; mi < 4; ++mi)
                ldsm4(af[mi], sA + SWZ(aRowOff[mi] + acol));
            #pragma unroll
            for (int nt = 0; nt < 2; ++nt) {
                uint32_t bf[4];
                ldsm4(bf, sB + SWZ(bRowOff[nt] + bcol));
                #pragma unroll
                for (int mi = 0; mi < 4; ++mi) {
                    mma_bf16(c[mi][2 * nt],     af[mi][0], af[mi][1], af[mi][2], af[mi][3], bf[0], bf[1]);
                    mma_bf16(c[mi][2 * nt + 1], af[mi][0], af[mi][1], af[mi][2], af[mi][3], bf[2], bf[3]);
                }
            }
        }
        if (kt + 2 < NKT) CP_WAIT1();
        __syncthreads();
    }
#undef PRODUCE

    // ---- epilogue: per-row (max, sumexp) over this 256-col tile ----
    const int colBase = bv * BN + wn * 32 + (lane & 3) * 2;

    #pragma unroll
    for (int mi = 0; mi < 4; ++mi) {
        int r0 = wm * 64 + mi * 16 + (lane >> 2);
        float mx0 = -1e30f, mx1 = -1e30f;
        #pragma unroll
        for (int ni = 0; ni < 4; ++ni) {
            int col = colBase + ni * 8;
            if (col < VOCAB)     { mx0 = fmaxf(mx0, c[mi][ni][0]); mx1 = fmaxf(mx1, c[mi][ni][2]); }
            if (col + 1 < VOCAB) { mx0 = fmaxf(mx0, c[mi][ni][1]); mx1 = fmaxf(mx1, c[mi][ni][3]); }
        }
        mx0 = fmaxf(mx0, __shfl_xor_sync(0xffffffffu, mx0, 1));
        mx0 = fmaxf(mx0, __shfl_xor_sync(0xffffffffu, mx0, 2));
        mx1 = fmaxf(mx1, __shfl_xor_sync(0xffffffffu, mx1, 1));
        mx1 = fmaxf(mx1, __shfl_xor_sync(0xffffffffu, mx1, 2));
        if ((lane & 3) == 0) {
            red_m[r0 * 8 + wn]       = mx0;
            red_m[(r0 + 8) * 8 + wn] = mx1;
        }
    }
    __syncthreads();

    #pragma unroll
    for (int mi = 0; mi < 4; ++mi) {
        int r0 = wm * 64 + mi * 16 + (lane >> 2);
        float rm0 = -1e30f, rm1 = -1e30f;
        #pragma unroll
        for (int i = 0; i < 8; ++i) {
            rm0 = fmaxf(rm0, red_m[r0 * 8 + i]);
            rm1 = fmaxf(rm1, red_m[(r0 + 8) * 8 + i]);
        }
        float s0 = 0.f, s1 = 0.f;
        #pragma unroll
        for (int ni = 0; ni < 4; ++ni) {
            int col = colBase + ni * 8;
            if (col < VOCAB)     { s0 += __expf(c[mi][ni][0] - rm0); s1 += __expf(c[mi][ni][2] - rm1); }
            if (col + 1 < VOCAB) { s0 += __expf(c[mi][ni][1] - rm0); s1 += __expf(c[mi][ni][3] - rm1); }
        }
        s0 += __shfl_xor_sync(0xffffffffu, s0, 1);
        s0 += __shfl_xor_sync(0xffffffffu, s0, 2);
        s1 += __shfl_xor_sync(0xffffffffu, s1, 1);
        s1 += __shfl_xor_sync(0xffffffffu, s1, 2);
        if ((lane & 3) == 0) {
            red_s[r0 * 8 + wn]       = s0;
            red_s[(r0 + 8) * 8 + wn] = s1;
        }
    }
    __syncthreads();

    if (tid < BM) {
        float rm = -1e30f, rs = 0.f;
        #pragma unroll
        for (int i = 0; i < 8; ++i) rm = fmaxf(rm, red_m[tid * 8 + i]);
        #pragma unroll
        for (int i = 0; i < 8; ++i) rs += red_s[tid * 8 + i];
        size_t row = (size_t)bm * BM + tid;
        g_pm[(size_t)bv * N_ROWS + row] = rm;
        g_ps[(size_t)bv * N_ROWS + row] = rs;
    }
}

// ---------------- combine partial (m, s) -> per-row loss ----------------
__global__ void combine_kernel() {
    int row = blockIdx.x * blockDim.x + threadIdx.x;
    if (row >= N_ROWS) return;
    float m = -1e30f;
    for (int i = 0; i < VT2; ++i)
        m = fmaxf(m, g_pm[(size_t)i * N_ROWS + row]);
    float s = 0.f;
    for (int i = 0; i < VT2; ++i)
        s += g_ps[(size_t)i * N_ROWS + row] * expf(g_pm[(size_t)i * N_ROWS + row] - m);
    g_loss[row] = (m + logf(s)) - g_tl[row];
}

// ---------------- mean reduction ----------------
__global__ void reduce_kernel(float* out) {
    float acc = 0.f;
    for (int i = threadIdx.x; i < N_ROWS; i += 256) acc += g_loss[i];
    #pragma unroll
    for (int off = 16; off > 0; off >>= 1)
        acc += __shfl_down_sync(0xffffffffu, acc, off);
    __shared__ float red[8];
    int lane = threadIdx.x & 31, wid = threadIdx.x >> 5;
    if (lane == 0) red[wid] = acc;
    __syncthreads();
    if (threadIdx.x == 0) {
        float t = 0.f;
        #pragma unroll
        for (int i = 0; i < 8; ++i) t += red[i];
        out[0] = t * (1.0f / N_ROWS);
    }
}

// ---------------- launch ----------------
extern "C" void kernel_launch(void* const* d_in, const int* in_sizes, int n_in,
                              void* d_out, int out_size) {
    const float* x = nullptr;
    const float* w = nullptr;
    const void* tgt = nullptr;
    for (int i = 0; i < n_in; ++i) {
        long long sz = in_sizes[i];
        if (sz == (long long)N_ROWS * DIM)      x   = (const float*)d_in[i];
        else if (sz == (long long)VOCAB * DIM)  w   = (const float*)d_in[i];
        else if (sz == (long long)N_ROWS)       tgt = d_in[i];
    }
    if (!x)   x   = (const float*)d_in[0];
    if (!w)   w   = (const float*)d_in[1];
    if (!tgt) tgt = d_in[2];
    float* out = (float*)d_out;

    cudaFuncSetAttribute(lse_kernel,
                         cudaFuncAttributeMaxDynamicSharedMemorySize, SM_TOTAL);

    long long w8 = (long long)VOCAB * DIM / 8;
    long long x8 = (long long)N_ROWS * DIM / 8;
    // NOTE: lse_kernel placed 4th in the launch sequence (the slot ncu's
    // -s 5 -c 1 capture has been landing on) so the profile finally shows
    // the GEMM kernel. tlogit is independent of lse; combine needs both.
    detect_kernel<<<1, 256>>>(tgt);
    cvt_kernel<<<(unsigned)((w8 + 255) / 256), 256>>>(w, w8, 0);
    cvt_kernel<<<(unsigned)((x8 + 255) / 256), 256>>>(x, x8, 1);
    lse_kernel<<<dim3(MT, VT2), 512, SM_TOTAL>>>();
    tlogit_kernel<<<N_ROWS, 128>>>(x, w, tgt);
    combine_kernel<<<(N_ROWS + 255) / 256, 256>>>();
    reduce_kernel<<<1, 256>>>(out);
}